// round 7
// baseline (speedup 1.0000x reference)
#include <cuda_runtime.h>
#include <math.h>

#define T_SEQ 512
#define NB    64
#define NI    256
#define NH    512

// Scratch: input projection result (64 MB).
__device__ float g_pre[(size_t)T_SEQ * NB * NH];

typedef unsigned long long ull;

// Packed 2x fp32 FMA (sm_10x f32x2 pipe): d = a*b + c elementwise on pairs.
#define FFMA2(d, a, b, c) \
    asm("fma.rn.f32x2 %0, %1, %2, %3;" : "=l"(d) : "l"(a), "l"(b), "l"(c))

__device__ __forceinline__ float2 unpack2(ull v) {
    unsigned lo, hi;
    asm("mov.b64 {%0, %1}, %2;" : "=r"(lo), "=r"(hi) : "l"(v));
    return make_float2(__uint_as_float(lo), __uint_as_float(hi));
}
__device__ __forceinline__ ull pack2(float lo, float hi) {
    ull r;
    asm("mov.b64 %0, {%1, %2};"
        : "=l"(r) : "r"(__float_as_uint(lo)), "r"(__float_as_uint(hi)));
    return r;
}

// ---- mbarrier helpers (cluster scope) -------------------------------------
__device__ __forceinline__ unsigned smem_u32(const void* p) {
    return (unsigned)__cvta_generic_to_shared(p);
}
__device__ __forceinline__ void mbar_init(unsigned addr, unsigned cnt) {
    asm volatile("mbarrier.init.shared.b64 [%0], %1;" :: "r"(addr), "r"(cnt)
                 : "memory");
}
// Arrive on the mbarrier at the same smem offset in cluster CTA `rank`.
__device__ __forceinline__ void mbar_arrive_rank(unsigned local_addr,
                                                 unsigned rank) {
    asm volatile(
        "{\n\t.reg .b32 ra;\n\t"
        "mapa.shared::cluster.u32 ra, %0, %1;\n\t"
        "mbarrier.arrive.shared::cluster.b64 _, [ra];\n\t}"
        :: "r"(local_addr), "r"(rank) : "memory");
}
// Spin-wait on local mbarrier for phase `parity` (acquire, cluster scope).
__device__ __forceinline__ void mbar_wait(unsigned addr, unsigned parity) {
    unsigned done;
    do {
        asm volatile(
            "{\n\t.reg .pred p;\n\t"
            "mbarrier.try_wait.parity.acquire.cluster.shared::cta.b64 p, [%1], %2, 0x989680;\n\t"
            "selp.b32 %0, 1, 0, p;\n\t}"
            : "=r"(done) : "r"(addr), "r"(parity) : "memory");
    } while (!done);
}

// ---------------------------------------------------------------------------
// GEMM: g_pre[m][j] = sum_k x[m][k] * W_ih[j][k] + b_ih[j] + b_hh[j]
// ---------------------------------------------------------------------------
#define BM 128
#define BN 64
#define BK 16

__global__ __launch_bounds__(256) void gemm_xw(
    const float* __restrict__ A,    // [M][256]
    const float* __restrict__ Wih,  // [512][256]
    const float* __restrict__ bih,
    const float* __restrict__ bhh)
{
    __shared__ float As[BK][BM + 4];
    __shared__ float Bs[BK][BN + 4];
    const int m0 = blockIdx.y * BM;
    const int n0 = blockIdx.x * BN;
    const int tid = threadIdx.x;
    const int ty = tid >> 4;
    const int tx = tid & 15;

    ull acc2[8][2];
#pragma unroll
    for (int i = 0; i < 8; ++i) { acc2[i][0] = 0ull; acc2[i][1] = 0ull; }

    for (int k0 = 0; k0 < NI; k0 += BK) {
#pragma unroll
        for (int i = 0; i < 2; ++i) {
            int f  = tid + i * 256;
            int r  = f >> 2;
            int c4 = f & 3;
            float4 v = *(const float4*)(A + (size_t)(m0 + r) * NI + k0 + c4 * 4);
            As[c4 * 4 + 0][r] = v.x;
            As[c4 * 4 + 1][r] = v.y;
            As[c4 * 4 + 2][r] = v.z;
            As[c4 * 4 + 3][r] = v.w;
        }
        {
            int r  = tid >> 2;
            int c4 = tid & 3;
            float4 v = *(const float4*)(Wih + (size_t)(n0 + r) * NI + k0 + c4 * 4);
            Bs[c4 * 4 + 0][r] = v.x;
            Bs[c4 * 4 + 1][r] = v.y;
            Bs[c4 * 4 + 2][r] = v.z;
            Bs[c4 * 4 + 3][r] = v.w;
        }
        __syncthreads();
#pragma unroll
        for (int k = 0; k < BK; ++k) {
            float a[8];
            *(float4*)&a[0] = *(const float4*)&As[k][ty * 8];
            *(float4*)&a[4] = *(const float4*)&As[k][ty * 8 + 4];
            ulonglong2 b2 = *(const ulonglong2*)&Bs[k][tx * 4];
#pragma unroll
            for (int i = 0; i < 8; ++i) {
                ull aa = pack2(a[i], a[i]);
                FFMA2(acc2[i][0], aa, b2.x, acc2[i][0]);
                FFMA2(acc2[i][1], aa, b2.y, acc2[i][1]);
            }
        }
        __syncthreads();
    }

    const int n = n0 + tx * 4;
    float4 bias = make_float4(bih[n + 0] + bhh[n + 0], bih[n + 1] + bhh[n + 1],
                              bih[n + 2] + bhh[n + 2], bih[n + 3] + bhh[n + 3]);
#pragma unroll
    for (int i = 0; i < 8; ++i) {
        float2 p0 = unpack2(acc2[i][0]);
        float2 p1 = unpack2(acc2[i][1]);
        float4 o;
        o.x = p0.x + bias.x;
        o.y = p0.y + bias.y;
        o.z = p1.x + bias.z;
        o.w = p1.y + bias.w;
        *(float4*)(g_pre + (size_t)(m0 + ty * 8 + i) * NH + n) = o;
    }
}

// ---------------------------------------------------------------------------
// Recurrence: 16 independent clusters of 8 CTAs; cluster g owns batches
// [4g,4g+4), rank r owns columns [64r,64r+64). Fine-grained dataflow sync:
// per-source-rank full mbarriers + per-parity empty mbarriers (double
// buffered), DSMEM chunk broadcast. No barrier.cluster in the loop.
// ---------------------------------------------------------------------------
#define CL 8
#define RT 512

__global__ __launch_bounds__(RT, 1) __cluster_dims__(CL, 1, 1)
void rnn_recur(
    const float* __restrict__ h0,    // [B][H]
    const float* __restrict__ Whh,   // [H][H]
    float* __restrict__ hseq,        // [T][B][H]
    float* __restrict__ hlast)       // [B][H] or nullptr
{
    __shared__ float hbuf[2][4 * NH];           // double-buffered h (16 KB)
    __shared__ float part[8 * 4 * 64];          // partials [ks][b][jj] (8 KB)
    __shared__ float hx[4 * 64];                // fresh local chunk (1 KB)
    __shared__ alignas(8) ull mb_full[8][2];    // [source rank][buf parity]
    __shared__ alignas(8) ull mb_empty[2];      // [buf parity]

    unsigned rank;
    asm("mov.u32 %0, %%cluster_ctarank;" : "=r"(rank));
    const int grp  = blockIdx.x >> 3;
    const int b0   = grp * 4;
    const int j0   = (int)rank * 64;
    const int tid  = threadIdx.x;
    const int lane = tid & 31;
    const int warp = tid >> 5;
    const int ks   = warp >> 1;                 // consumed k-slice 0..7
    const int k0   = ks * 64;
    const int jj   = (warp & 1) * 32 + lane;
    const int j    = j0 + jj;

    const unsigned a_full_mine0 = smem_u32(&mb_full[rank][0]);  // in peers
    const unsigned a_full_ks0   = smem_u32(&mb_full[ks][0]);    // local wait
    const unsigned a_empty0     = smem_u32(&mb_empty[0]);

    if (tid == 0) {
#pragma unroll
        for (int s = 0; s < 8; ++s) {
            mbar_init(smem_u32(&mb_full[s][0]), 1);
            mbar_init(smem_u32(&mb_full[s][1]), 1);
        }
        mbar_init(a_empty0, 16);
        mbar_init(a_empty0 + 8, 16);
    }

    // W_hh[j][k0..k0+63] -> 32 packed-pair registers.
    ull w2[32];
    {
        const ulonglong2* wp = (const ulonglong2*)(Whh + (size_t)j * NH + k0);
#pragma unroll
        for (int c = 0; c < 16; ++c) {
            ulonglong2 v = __ldg(wp + c);
            w2[2 * c]     = v.x;
            w2[2 * c + 1] = v.y;
        }
    }

    // Fill hbuf[0] with h0 rows b0..b0+3 (local copy of full H).
    {
        int row = tid >> 7;
        int c4  = tid & 127;
        *(float4*)&hbuf[0][row * NH + c4 * 4] =
            __ldg((const float4*)(h0 + (size_t)(b0 + row) * NH + c4 * 4));
    }
    __syncthreads();
    // mbarriers + hbuf visible before any remote traffic.
    asm volatile("barrier.cluster.arrive.aligned;" ::: "memory");
    asm volatile("barrier.cluster.wait.aligned;"   ::: "memory");

    // Sender map: thread sends float4 #xidx of our chunk to rank dst.
    const int dst   = tid >> 6;          // 0..7
    const int xidx  = tid & 63;
    const int xb    = xidx >> 4;
    const int xc4   = xidx & 15;

    // Reducer map (warps 0..7).
    const int rb  = warp >> 1;
    const int rjl = (warp & 1) * 32 + lane;

    float pre = 0.f;
    if (warp < 8)
        pre = __ldg(g_pre + ((size_t)0 * NB + (b0 + rb)) * NH + j0 + rjl);

    unsigned phf0 = 0, phf1 = 0;   // consumer phases for full[ks][0/1]
    unsigned phe0 = 0, phe1 = 0;   // producer phases for empty[0/1]

    for (int t = 0; t < T_SEQ; ++t) {
        const int p = t & 1;         // buffer being read
        const int q = p ^ 1;         // buffer being written

        // -- Consume: wait for my slice of buf p (producer arrived at t-1). --
        if (t > 0) {
            if (p) { mbar_wait(a_full_ks0 + 8, phf1); phf1 ^= 1; }
            else   { mbar_wait(a_full_ks0,     phf0); phf0 ^= 1; }
        }

        const float* cur = hbuf[p];
        float accs[4];
#pragma unroll
        for (int b = 0; b < 4; ++b) {
            const ulonglong2* hp = (const ulonglong2*)(cur + b * NH + k0);
            ull a0 = 0ull, a1 = 0ull;
#pragma unroll
            for (int c = 0; c < 16; ++c) {
                ulonglong2 hv = hp[c];   // broadcast LDS.128
                FFMA2(a0, w2[2 * c],     hv.x, a0);
                FFMA2(a1, w2[2 * c + 1], hv.y, a1);
            }
            float2 f0 = unpack2(a0);
            float2 f1 = unpack2(a1);
            accs[b] = (f0.x + f0.y) + (f1.x + f1.y);
        }
        // Done reading buf p: tell its producer (rank ks) it's free.
        __syncwarp();
        if (t < T_SEQ - 2 && lane == 0)
            mbar_arrive_rank(a_empty0 + (unsigned)p * 8, (unsigned)ks);

#pragma unroll
        for (int b = 0; b < 4; ++b)
            part[ks * 256 + b * 64 + jj] = accs[b];
        __syncthreads();

        // -- Reduce + tanh + emit (warps 0..7). --
        if (warp < 8) {
            float s = 0.f;
#pragma unroll
            for (int w = 0; w < 8; ++w)
                s += part[w * 256 + rb * 64 + rjl];
            const float hv = tanhf(s + pre);
            const int   bo = b0 + rb;
            hseq[((size_t)t * NB + bo) * NH + j0 + rjl] = hv;
            if (t == T_SEQ - 1 && hlast) hlast[(size_t)bo * NH + j0 + rjl] = hv;
            hx[rb * 64 + rjl] = hv;
        }
        __syncthreads();

        // -- Produce: broadcast our chunk into every rank's buf q. --
        if (t < T_SEQ - 1) {
            if (t >= 1) {   // buf q's previous readers (step t-1) must be done
                if (q) { mbar_wait(a_empty0 + 8, phe1); phe1 ^= 1; }
                else   { mbar_wait(a_empty0,     phe0); phe0 ^= 1; }
            }
            {
                float4 v = *(const float4*)&hx[xidx * 4];
                unsigned loc = smem_u32(&hbuf[q][xb * NH + j0 + xc4 * 4]);
                unsigned da;
                asm("mapa.shared::cluster.u32 %0, %1, %2;"
                    : "=r"(da) : "r"(loc), "r"((unsigned)dst));
                asm volatile("st.shared::cluster.v4.b32 [%0], {%1,%2,%3,%4};"
                             :: "r"(da), "f"(v.x), "f"(v.y), "f"(v.z), "f"(v.w)
                             : "memory");
            }
            __syncthreads();   // all 64 stores per destination complete
            if ((tid & 63) == 0) {
                asm volatile("fence.acq_rel.cluster;" ::: "memory");
                mbar_arrive_rank(a_full_mine0 + (unsigned)q * 8, (unsigned)dst);
            }
            // Prefetch next step's pre-activation (off critical path).
            if (warp < 8)
                pre = __ldg(g_pre + ((size_t)(t + 1) * NB + (b0 + rb)) * NH
                            + j0 + rjl);
        }
    }

    // Keep smem alive until all peers are done with remote ops.
    asm volatile("barrier.cluster.arrive.aligned;" ::: "memory");
    asm volatile("barrier.cluster.wait.aligned;"   ::: "memory");
}

// ---------------------------------------------------------------------------
extern "C" void kernel_launch(void* const* d_in, const int* in_sizes, int n_in,
                              void* d_out, int out_size)
{
    const float* x   = (const float*)d_in[0];
    const float* h0  = (const float*)d_in[1];
    const float* Wih = (const float*)d_in[2];
    const float* Whh = (const float*)d_in[3];
    const float* bih = (const float*)d_in[4];
    const float* bhh = (const float*)d_in[5];
    float* out = (float*)d_out;

    float* hlast = nullptr;
    if (out_size >= (int)((size_t)T_SEQ * NB * NH + NB * NH))
        hlast = out + (size_t)T_SEQ * NB * NH;

    dim3 grid(NH / BN, (T_SEQ * NB) / BM);   // (8, 256)
    gemm_xw<<<grid, 256>>>(x, Wih, bih, bhh);

    rnn_recur<<<128, RT>>>(h0, Whh, out, hlast);
}

// round 8
// speedup vs baseline: 1.3692x; 1.3692x over previous
#include <cuda_runtime.h>
#include <math.h>

#define T_SEQ 512
#define NB    64
#define NI    256
#define NH    512

// Scratch: input projection result (64 MB) + barrier counter.
__device__ float    g_pre[(size_t)T_SEQ * NB * NH];
__device__ unsigned g_bar;

__global__ void reset_bar() { g_bar = 0u; }

typedef unsigned long long ull;

// Packed 2x fp32 FMA (sm_10x f32x2 pipe): d = a*b + c elementwise on pairs.
#define FFMA2(d, a, b, c) \
    asm("fma.rn.f32x2 %0, %1, %2, %3;" : "=l"(d) : "l"(a), "l"(b), "l"(c))

__device__ __forceinline__ ull pack2(float lo, float hi) {
    ull r;
    asm("mov.b64 %0, {%1, %2};"
        : "=l"(r) : "r"(__float_as_uint(lo)), "r"(__float_as_uint(hi)));
    return r;
}
__device__ __forceinline__ float2 unpack2(ull v) {
    unsigned lo, hi;
    asm("mov.b64 {%0, %1}, %2;" : "=r"(lo), "=r"(hi) : "l"(v));
    return make_float2(__uint_as_float(lo), __uint_as_float(hi));
}

// ---------------------------------------------------------------------------
// GEMM: g_pre[m][j] = sum_k x[m][k] * W_ih[j][k] + b_ih[j] + b_hh[j]
// M = T*B = 32768, N = 512, K = 256.  BM=128, BN=64, BK=16, 256 thr, 8x4 micro.
// ---------------------------------------------------------------------------
#define BM 128
#define BN 64
#define BK 16

__global__ __launch_bounds__(256) void gemm_xw(
    const float* __restrict__ A,    // [M][256]
    const float* __restrict__ Wih,  // [512][256]
    const float* __restrict__ bih,
    const float* __restrict__ bhh)
{
    __shared__ float As[BK][BM + 4];
    __shared__ float Bs[BK][BN + 4];
    const int m0 = blockIdx.y * BM;
    const int n0 = blockIdx.x * BN;
    const int tid = threadIdx.x;
    const int ty = tid >> 4;
    const int tx = tid & 15;

    ull acc2[8][2];
#pragma unroll
    for (int i = 0; i < 8; ++i) { acc2[i][0] = 0ull; acc2[i][1] = 0ull; }

    for (int k0 = 0; k0 < NI; k0 += BK) {
#pragma unroll
        for (int i = 0; i < 2; ++i) {
            int f  = tid + i * 256;
            int r  = f >> 2;
            int c4 = f & 3;
            float4 v = *(const float4*)(A + (size_t)(m0 + r) * NI + k0 + c4 * 4);
            As[c4 * 4 + 0][r] = v.x;
            As[c4 * 4 + 1][r] = v.y;
            As[c4 * 4 + 2][r] = v.z;
            As[c4 * 4 + 3][r] = v.w;
        }
        {
            int r  = tid >> 2;
            int c4 = tid & 3;
            float4 v = *(const float4*)(Wih + (size_t)(n0 + r) * NI + k0 + c4 * 4);
            Bs[c4 * 4 + 0][r] = v.x;
            Bs[c4 * 4 + 1][r] = v.y;
            Bs[c4 * 4 + 2][r] = v.z;
            Bs[c4 * 4 + 3][r] = v.w;
        }
        __syncthreads();
#pragma unroll
        for (int k = 0; k < BK; ++k) {
            float a[8];
            *(float4*)&a[0] = *(const float4*)&As[k][ty * 8];
            *(float4*)&a[4] = *(const float4*)&As[k][ty * 8 + 4];
            ulonglong2 b2 = *(const ulonglong2*)&Bs[k][tx * 4];
#pragma unroll
            for (int i = 0; i < 8; ++i) {
                ull aa = pack2(a[i], a[i]);
                FFMA2(acc2[i][0], aa, b2.x, acc2[i][0]);
                FFMA2(acc2[i][1], aa, b2.y, acc2[i][1]);
            }
        }
        __syncthreads();
    }

    const int n = n0 + tx * 4;
    float4 bias = make_float4(bih[n + 0] + bhh[n + 0], bih[n + 1] + bhh[n + 1],
                              bih[n + 2] + bhh[n + 2], bih[n + 3] + bhh[n + 3]);
#pragma unroll
    for (int i = 0; i < 8; ++i) {
        float2 p0 = unpack2(acc2[i][0]);
        float2 p1 = unpack2(acc2[i][1]);
        float4 o;
        o.x = p0.x + bias.x;
        o.y = p0.y + bias.y;
        o.z = p1.x + bias.z;
        o.w = p1.y + bias.w;
        *(float4*)(g_pre + (size_t)(m0 + ty * 8 + i) * NH + n) = o;
    }
}

// ---------------------------------------------------------------------------
// Persistent recurrence kernel: 128 CTAs (16 j-tiles x 8 b-tiles), 256 thr.
// Thread (lane=j, warp=k-slice of 64) holds W_hh[j][kslice] in 64 registers.
// Grid barrier: flat monotonic counter, CG-style — bar.sync, thread0
// red.release.gpu arrive + ld.acquire.gpu poll, bar.sync. No MEMBAR.GPU.
// pre(t+1) prefetched before arrival so its DRAM latency hides under the
// barrier wait + next step's staging.
// ---------------------------------------------------------------------------
#define RG 128
#define RT 256

__global__ __launch_bounds__(RT, 1) void rnn_recur(
    const float* __restrict__ h0,    // [B][H]
    const float* __restrict__ Whh,   // [H][H]
    float* __restrict__ hseq,        // [T][B][H]
    float* __restrict__ hlast)       // [B][H] or nullptr
{
    __shared__ float hs[8 * NH];          // staged h_{t-1} tile (16 KB)
    __shared__ float part[8 * 8 * 32];    // partials [kslice][b][lane] (8 KB)

    const int jt   = blockIdx.x & 15;
    const int bt   = blockIdx.x >> 4;
    const int j0   = jt * 32;
    const int b0   = bt * 8;
    const int lane = threadIdx.x & 31;
    const int warp = threadIdx.x >> 5;
    const int j    = j0 + lane;           // output column this thread owns
    const int k0   = warp * 64;           // k-slice this warp owns

    // W_hh[j][k0 .. k0+63] -> 32 packed-pair registers (lives whole kernel).
    ull w2[32];
    {
        const ulonglong2* wp = (const ulonglong2*)(Whh + (size_t)j * NH + k0);
#pragma unroll
        for (int c = 0; c < 16; ++c) {
            ulonglong2 v = __ldg(wp + c);
            w2[2 * c]     = v.x;
            w2[2 * c + 1] = v.y;
        }
    }

    const float* hprev = h0;

    // Step-0 pre-activation (reducer identity of this thread: b=b0+warp, j).
    float pre = __ldg(g_pre + ((size_t)0 * NB + (b0 + warp)) * NH + j);

    for (int t = 0; t < T_SEQ; ++t) {
        // Stage h_{t-1} tile (8 x 512 floats) L2 -> smem.
#pragma unroll
        for (int r = 0; r < 4; ++r) {
            int idx = threadIdx.x + r * RT;   // 0..1023 float4 slots
            int row = idx >> 7;
            int c4  = idx & 127;
            *(float4*)(hs + row * NH + c4 * 4) =
                __ldcg((const float4*)(hprev + (size_t)(b0 + row) * NH + c4 * 4));
        }
        __syncthreads();

        // 8 partial dot products (one per batch), K-slice of 64, packed FMAs.
        float accs[8];
#pragma unroll
        for (int b = 0; b < 8; ++b) {
            const ulonglong2* hp = (const ulonglong2*)(hs + b * NH + k0);
            ull a0 = 0ull, a1 = 0ull;
#pragma unroll
            for (int c = 0; c < 16; ++c) {
                ulonglong2 hv = hp[c];   // broadcast LDS.128
                FFMA2(a0, w2[2 * c],     hv.x, a0);
                FFMA2(a1, w2[2 * c + 1], hv.y, a1);
            }
            float2 f0 = unpack2(a0);
            float2 f1 = unpack2(a1);
            accs[b] = (f0.x + f0.y) + (f1.x + f1.y);
        }

        // Cross-warp reduction: part[warp][b][lane], conflict-free both ways.
#pragma unroll
        for (int b = 0; b < 8; ++b)
            part[warp * 256 + b * 32 + lane] = accs[b];
        __syncthreads();

        float s = 0.f;
#pragma unroll
        for (int w = 0; w < 8; ++w)
            s += part[w * 256 + warp * 32 + lane];

        const float hv = tanhf(s + pre);
        const int   bo = b0 + warp;
        hseq[((size_t)t * NB + bo) * NH + j] = hv;
        if (t == T_SEQ - 1 && hlast) hlast[(size_t)bo * NH + j] = hv;

        // Prefetch next step's pre-activation (latency hides under barrier).
        if (t + 1 < T_SEQ)
            pre = __ldg(g_pre + ((size_t)(t + 1) * NB + bo) * NH + j);

        // --- Grid barrier (cooperative-groups style, no MEMBAR.GPU). ---
        __syncthreads();   // all threads' h stores program-ordered before red
        if (threadIdx.x == 0) {
            asm volatile("red.release.gpu.global.add.u32 [%0], 1;"
                         :: "l"(&g_bar) : "memory");
            const unsigned target = (unsigned)(t + 1) * RG;
            unsigned f;
            do {
                asm volatile("ld.acquire.gpu.u32 %0, [%1];"
                             : "=r"(f) : "l"(&g_bar) : "memory");
            } while (f < target);
        }
        __syncthreads();   // propagate acquire to whole CTA

        hprev = hseq + (size_t)t * NB * NH;
    }
}

// ---------------------------------------------------------------------------
extern "C" void kernel_launch(void* const* d_in, const int* in_sizes, int n_in,
                              void* d_out, int out_size)
{
    const float* x   = (const float*)d_in[0];
    const float* h0  = (const float*)d_in[1];
    const float* Wih = (const float*)d_in[2];
    const float* Whh = (const float*)d_in[3];
    const float* bih = (const float*)d_in[4];
    const float* bhh = (const float*)d_in[5];
    float* out = (float*)d_out;

    float* hlast = nullptr;
    if (out_size >= (int)((size_t)T_SEQ * NB * NH + NB * NH))
        hlast = out + (size_t)T_SEQ * NB * NH;

    reset_bar<<<1, 1>>>();

    dim3 grid(NH / BN, (T_SEQ * NB) / BM);   // (8, 256)
    gemm_xw<<<grid, 256>>>(x, Wih, bih, bhh);

    rnn_recur<<<RG, RT>>>(h0, Whh, out, hlast);
}

// round 9
// speedup vs baseline: 1.4002x; 1.0226x over previous
#include <cuda_runtime.h>
#include <math.h>

#define T_SEQ 512
#define NB    64
#define NI    256
#define NH    512

// Scratch: input projection result (64 MB) + per-group barrier counters.
__device__ float    g_pre[(size_t)T_SEQ * NB * NH];
__device__ unsigned g_barg[8 * 64];   // 8 counters, 256 B apart (distinct LTS)

typedef unsigned long long ull;

// Packed 2x fp32 FMA (sm_10x f32x2 pipe): d = a*b + c elementwise on pairs.
#define FFMA2(d, a, b, c) \
    asm("fma.rn.f32x2 %0, %1, %2, %3;" : "=l"(d) : "l"(a), "l"(b), "l"(c))

__device__ __forceinline__ ull pack2(float lo, float hi) {
    ull r;
    asm("mov.b64 %0, {%1, %2};"
        : "=l"(r) : "r"(__float_as_uint(lo)), "r"(__float_as_uint(hi)));
    return r;
}
__device__ __forceinline__ float2 unpack2(ull v) {
    unsigned lo, hi;
    asm("mov.b64 {%0, %1}, %2;" : "=r"(lo), "=r"(hi) : "l"(v));
    return make_float2(__uint_as_float(lo), __uint_as_float(hi));
}

// ---------------------------------------------------------------------------
// GEMM: g_pre[m][j] = sum_k x[m][k] * W_ih[j][k] + b_ih[j] + b_hh[j]
// M = T*B = 32768, N = 512, K = 256.  BM=128, BN=64, BK=16, 256 thr, 8x4 micro.
// Block (0,0) also zeroes the barrier counters (runs before rnn_recur).
// ---------------------------------------------------------------------------
#define BM 128
#define BN 64
#define BK 16

__global__ __launch_bounds__(256) void gemm_xw(
    const float* __restrict__ A,    // [M][256]
    const float* __restrict__ Wih,  // [512][256]
    const float* __restrict__ bih,
    const float* __restrict__ bhh)
{
    __shared__ float As[BK][BM + 4];
    __shared__ float Bs[BK][BN + 4];
    const int m0 = blockIdx.y * BM;
    const int n0 = blockIdx.x * BN;
    const int tid = threadIdx.x;
    const int ty = tid >> 4;
    const int tx = tid & 15;

    if (blockIdx.x == 0 && blockIdx.y == 0 && tid < 8)
        g_barg[tid * 64] = 0u;

    ull acc2[8][2];
#pragma unroll
    for (int i = 0; i < 8; ++i) { acc2[i][0] = 0ull; acc2[i][1] = 0ull; }

    for (int k0 = 0; k0 < NI; k0 += BK) {
#pragma unroll
        for (int i = 0; i < 2; ++i) {
            int f  = tid + i * 256;
            int r  = f >> 2;
            int c4 = f & 3;
            float4 v = *(const float4*)(A + (size_t)(m0 + r) * NI + k0 + c4 * 4);
            As[c4 * 4 + 0][r] = v.x;
            As[c4 * 4 + 1][r] = v.y;
            As[c4 * 4 + 2][r] = v.z;
            As[c4 * 4 + 3][r] = v.w;
        }
        {
            int r  = tid >> 2;
            int c4 = tid & 3;
            float4 v = *(const float4*)(Wih + (size_t)(n0 + r) * NI + k0 + c4 * 4);
            Bs[c4 * 4 + 0][r] = v.x;
            Bs[c4 * 4 + 1][r] = v.y;
            Bs[c4 * 4 + 2][r] = v.z;
            Bs[c4 * 4 + 3][r] = v.w;
        }
        __syncthreads();
#pragma unroll
        for (int k = 0; k < BK; ++k) {
            float a[8];
            *(float4*)&a[0] = *(const float4*)&As[k][ty * 8];
            *(float4*)&a[4] = *(const float4*)&As[k][ty * 8 + 4];
            ulonglong2 b2 = *(const ulonglong2*)&Bs[k][tx * 4];
#pragma unroll
            for (int i = 0; i < 8; ++i) {
                ull aa = pack2(a[i], a[i]);
                FFMA2(acc2[i][0], aa, b2.x, acc2[i][0]);
                FFMA2(acc2[i][1], aa, b2.y, acc2[i][1]);
            }
        }
        __syncthreads();
    }

    const int n = n0 + tx * 4;
    float4 bias = make_float4(bih[n + 0] + bhh[n + 0], bih[n + 1] + bhh[n + 1],
                              bih[n + 2] + bhh[n + 2], bih[n + 3] + bhh[n + 3]);
#pragma unroll
    for (int i = 0; i < 8; ++i) {
        float2 p0 = unpack2(acc2[i][0]);
        float2 p1 = unpack2(acc2[i][1]);
        float4 o;
        o.x = p0.x + bias.x;
        o.y = p0.y + bias.y;
        o.z = p1.x + bias.z;
        o.w = p1.y + bias.w;
        *(float4*)(g_pre + (size_t)(m0 + ty * 8 + i) * NH + n) = o;
    }
}

// ---------------------------------------------------------------------------
// Persistent recurrence kernel: 128 CTAs (16 j-tiles x 8 b-tiles), 256 thr.
// Thread (lane=j, warp=k-slice of 64) holds W_hh[j][kslice] in 64 registers.
// KEY: CTA (jt,bt) consumes only h rows of batch group bt, produced by the
// 16 CTAs sharing bt -> barrier scope is 16 CTAs, not 128. One flat counter
// per group (8 counters, 256 B apart), CG-style arrive/poll, no MEMBAR.
// ---------------------------------------------------------------------------
#define RG 128
#define RT 256

__global__ __launch_bounds__(RT, 1) void rnn_recur(
    const float* __restrict__ h0,    // [B][H]
    const float* __restrict__ Whh,   // [H][H]
    float* __restrict__ hseq,        // [T][B][H]
    float* __restrict__ hlast)       // [B][H] or nullptr
{
    __shared__ float hs[8 * NH];          // staged h_{t-1} tile (16 KB)
    __shared__ float part[8 * 8 * 32];    // partials [kslice][b][lane] (8 KB)

    const int jt   = blockIdx.x & 15;
    const int bt   = blockIdx.x >> 4;
    const int j0   = jt * 32;
    const int b0   = bt * 8;
    const int lane = threadIdx.x & 31;
    const int warp = threadIdx.x >> 5;
    const int j    = j0 + lane;           // output column this thread owns
    const int k0   = warp * 64;           // k-slice this warp owns
    unsigned* const bar = &g_barg[bt * 64];

    // W_hh[j][k0 .. k0+63] -> 32 packed-pair registers (lives whole kernel).
    ull w2[32];
    {
        const ulonglong2* wp = (const ulonglong2*)(Whh + (size_t)j * NH + k0);
#pragma unroll
        for (int c = 0; c < 16; ++c) {
            ulonglong2 v = __ldg(wp + c);
            w2[2 * c]     = v.x;
            w2[2 * c + 1] = v.y;
        }
    }

    const float* hprev = h0;

    // Step-0 pre-activation (reducer identity of this thread: b=b0+warp, j).
    float pre = __ldg(g_pre + ((size_t)0 * NB + (b0 + warp)) * NH + j);

    for (int t = 0; t < T_SEQ; ++t) {
        // Stage h_{t-1} tile (8 x 512 floats) L2 -> smem.
#pragma unroll
        for (int r = 0; r < 4; ++r) {
            int idx = threadIdx.x + r * RT;   // 0..1023 float4 slots
            int row = idx >> 7;
            int c4  = idx & 127;
            *(float4*)(hs + row * NH + c4 * 4) =
                __ldcg((const float4*)(hprev + (size_t)(b0 + row) * NH + c4 * 4));
        }
        __syncthreads();

        // 8 partial dot products (one per batch), K-slice of 64, packed FMAs.
        float accs[8];
#pragma unroll
        for (int b = 0; b < 8; ++b) {
            const ulonglong2* hp = (const ulonglong2*)(hs + b * NH + k0);
            ull a0 = 0ull, a1 = 0ull;
#pragma unroll
            for (int c = 0; c < 16; ++c) {
                ulonglong2 hv = hp[c];   // broadcast LDS.128
                FFMA2(a0, w2[2 * c],     hv.x, a0);
                FFMA2(a1, w2[2 * c + 1], hv.y, a1);
            }
            float2 f0 = unpack2(a0);
            float2 f1 = unpack2(a1);
            accs[b] = (f0.x + f0.y) + (f1.x + f1.y);
        }

        // Cross-warp reduction: part[warp][b][lane], conflict-free both ways.
#pragma unroll
        for (int b = 0; b < 8; ++b)
            part[warp * 256 + b * 32 + lane] = accs[b];
        __syncthreads();

        float s = 0.f;
#pragma unroll
        for (int w = 0; w < 8; ++w)
            s += part[w * 256 + warp * 32 + lane];

        const float hv = tanhf(s + pre);
        const int   bo = b0 + warp;
        hseq[((size_t)t * NB + bo) * NH + j] = hv;
        if (t == T_SEQ - 1 && hlast) hlast[(size_t)bo * NH + j] = hv;

        // Prefetch next step's pre-activation (latency hides under barrier).
        if (t + 1 < T_SEQ)
            pre = __ldg(g_pre + ((size_t)(t + 1) * NB + bo) * NH + j);

        // --- Group barrier: only the 16 CTAs sharing this batch group. ---
        __syncthreads();   // all threads' h stores program-ordered before red
        if (threadIdx.x == 0) {
            asm volatile("red.release.gpu.global.add.u32 [%0], 1;"
                         :: "l"(bar) : "memory");
            const unsigned target = (unsigned)(t + 1) * 16u;
            unsigned f;
            do {
                asm volatile("ld.acquire.gpu.u32 %0, [%1];"
                             : "=r"(f) : "l"(bar) : "memory");
            } while (f < target);
        }
        __syncthreads();   // propagate acquire to whole CTA

        hprev = hseq + (size_t)t * NB * NH;
    }
}

// ---------------------------------------------------------------------------
extern "C" void kernel_launch(void* const* d_in, const int* in_sizes, int n_in,
                              void* d_out, int out_size)
{
    const float* x   = (const float*)d_in[0];
    const float* h0  = (const float*)d_in[1];
    const float* Wih = (const float*)d_in[2];
    const float* Whh = (const float*)d_in[3];
    const float* bih = (const float*)d_in[4];
    const float* bhh = (const float*)d_in[5];
    float* out = (float*)d_out;

    float* hlast = nullptr;
    if (out_size >= (int)((size_t)T_SEQ * NB * NH + NB * NH))
        hlast = out + (size_t)T_SEQ * NB * NH;

    dim3 grid(NH / BN, (T_SEQ * NB) / BM);   // (8, 256)
    gemm_xw<<<grid, 256>>>(x, Wih, bih, bhh);

    rnn_recur<<<RG, RT>>>(h0, Whh, out, hlast);
}